// round 10
// baseline (speedup 1.0000x reference)
#include <cuda_runtime.h>
#include <cuda_fp16.h>
#include <cstdint>

#define B_  2
#define S_  2048
#define D_  1024
#define H_  16
#define HD_ 64
#define M_  (B_ * S_)   // 4096

// ---------------- device scratch (no cudaMalloc allowed) ----------------
__device__ __half g_xh[(size_t)M_ * D_];           // x rounded
__device__ __half g_wh[(size_t)3 * D_ * D_];       // w_qkv rounded
__device__ __half g_woh[(size_t)D_ * D_];          // w_o rounded
__device__ __half g_qkv[(size_t)M_ * 3 * D_];      // qkv fp16 (q pre-scaled by 0.125*log2e)
__device__ __half g_ah[(size_t)M_ * D_];           // attn out fp16

// ---------------- PTX helpers (sm_80+ portable) ----------------
__device__ __forceinline__ uint32_t smem_u32(const void* p) {
    uint32_t a;
    asm("{ .reg .u64 t; cvta.to.shared.u64 t, %1; cvt.u32.u64 %0, t; }"
        : "=r"(a) : "l"(p));
    return a;
}

#define CPA16(saddr, gptr) \
    asm volatile("cp.async.cg.shared.global [%0], [%1], 16;" \
                 :: "r"(saddr), "l"(gptr) : "memory")
#define CPA_COMMIT() asm volatile("cp.async.commit_group;" ::: "memory")
#define CPA_WAIT(n)  asm volatile("cp.async.wait_group %0;" :: "n"(n) : "memory")

#define LDSM_X4(r, addr) \
    asm volatile("ldmatrix.sync.aligned.m8n8.x4.shared.b16 {%0,%1,%2,%3}, [%4];" \
                 : "=r"((r)[0]), "=r"((r)[1]), "=r"((r)[2]), "=r"((r)[3]) \
                 : "r"(addr))
#define LDSM_X4T(r, addr) \
    asm volatile("ldmatrix.sync.aligned.m8n8.x4.trans.shared.b16 {%0,%1,%2,%3}, [%4];" \
                 : "=r"((r)[0]), "=r"((r)[1]), "=r"((r)[2]), "=r"((r)[3]) \
                 : "r"(addr))

#define MMAH(c, a, b) \
    asm volatile("mma.sync.aligned.m16n8k16.row.col.f32.f16.f16.f32 " \
                 "{%0,%1,%2,%3}, {%4,%5,%6,%7}, {%8,%9}, {%0,%1,%2,%3};" \
                 : "+f"((c)[0]), "+f"((c)[1]), "+f"((c)[2]), "+f"((c)[3]) \
                 : "r"((a)[0]), "r"((a)[1]), "r"((a)[2]), "r"((a)[3]), \
                   "r"((b)[0]), "r"((b)[1]))

// ---------------------------------------------------------------------------
// fused prep: round x, w_qkv, w_o to fp16 in one grid-stride launch
// ---------------------------------------------------------------------------
#define N4_X   (M_ * D_ / 4)
#define N4_W   (3 * D_ * D_ / 4)
#define N4_WO  (D_ * D_ / 4)
#define N4_ALL (N4_X + N4_W + N4_WO)

__global__ void __launch_bounds__(256)
prep_kernel(const float4* __restrict__ x, const float4* __restrict__ w,
            const float4* __restrict__ wo, __half2* __restrict__ xh,
            __half2* __restrict__ wh, __half2* __restrict__ woh)
{
    int i = blockIdx.x * 256 + threadIdx.x;
    if (i >= N4_ALL) return;
    const float4* src;
    __half2* dst;
    int j;
    if (i < N4_X)            { src = x;  dst = xh;  j = i; }
    else if (i < N4_X + N4_W){ src = w;  dst = wh;  j = i - N4_X; }
    else                     { src = wo; dst = woh; j = i - N4_X - N4_W; }
    float4 v = src[j];
    dst[2 * j]     = __floats2half2_rn(v.x, v.y);
    dst[2 * j + 1] = __floats2half2_rn(v.z, v.w);
}

// ---------------------------------------------------------------------------
// Tensor-core GEMM, fp16: C = Ah[M,K] @ Bh[N,K]^T + bias.
// SPLIT_OUT: +RoPE (+0.125*log2e q scale), writes fp16. Else fp32 + bias.
// 128x128 CTA tile, 8 warps (2m x 4n), BK=64 per pipeline step, 3-stage ring
// (one barrier per 64-K). Row stride 72 halfs (144 B, conflict-free ldmatrix).
// ---------------------------------------------------------------------------
#define BKC      64
#define GSTR2    144                    // bytes per row (72 halfs)
#define GPART    (128 * GSTR2)          // 18432 B per matrix per stage
#define GSTAGE   (2 * GPART)            // 36864
#define GSMEM    (3 * GSTAGE)           // 110592

#define QSCALE   0.18033688011112042f   // 0.125 * log2(e)

template <bool SPLIT_OUT>
__global__ void __launch_bounds__(256, 2)
gemm_mma(const __half* __restrict__ Ah, const __half* __restrict__ Bh,
         const float* __restrict__ bias, const float* __restrict__ rot,
         float* __restrict__ C, __half* __restrict__ Ch, int M, int N, int K)
{
    extern __shared__ __align__(16) char smem[];
    const uint32_t sb = smem_u32(smem);

    const int tid  = threadIdx.x;
    const int wid  = tid >> 5;
    const int lane = tid & 31;
    const int g    = lane >> 2;
    const int tg   = lane & 3;
    const int m0   = (wid & 1) * 64;
    const int n0   = (wid >> 1) * 32;

    // loader: 2 threads per row, each 64 B (4 x 16B)
    const int lrow = tid >> 1;
    const int lhalf = (tid & 1);                  // 0 or 1
    const uint32_t so = (uint32_t)lrow * GSTR2 + lhalf * 64;

    const size_t rA = (size_t)(blockIdx.y * 128 + lrow) * K + lhalf * 32;
    const size_t rB = (size_t)(blockIdx.x * 128 + lrow) * K + lhalf * 32;
    const __half* pAh = Ah + rA;
    const __half* pBh = Bh + rB;

    const uint32_t laneA  = (uint32_t)(lane & 15) * GSTR2 + (lane >> 4) * 16;
    const uint32_t laneB4 = (uint32_t)(lane & 7) * GSTR2 + ((lane >> 3) & 1) * 16
                          + (uint32_t)(lane >> 4) * 8 * GSTR2;

    float c[4][4][4];
#pragma unroll
    for (int mi = 0; mi < 4; mi++)
#pragma unroll
        for (int ni = 0; ni < 4; ni++)
#pragma unroll
            for (int e = 0; e < 4; e++) c[mi][ni][e] = 0.0f;

    const int NT = K / BKC;   // 16

    auto issue = [&](int t) {
        const uint32_t sbase = sb + (t % 3) * GSTAGE;
        const size_t k0 = (size_t)t * BKC;
        CPA16(sbase + so,               pAh + k0);
        CPA16(sbase + so + 16,          pAh + k0 + 8);
        CPA16(sbase + so + 32,          pAh + k0 + 16);
        CPA16(sbase + so + 48,          pAh + k0 + 24);
        CPA16(sbase + GPART + so,       pBh + k0);
        CPA16(sbase + GPART + so + 16,  pBh + k0 + 8);
        CPA16(sbase + GPART + so + 32,  pBh + k0 + 16);
        CPA16(sbase + GPART + so + 48,  pBh + k0 + 24);
        CPA_COMMIT();
    };

    issue(0);
    issue(1);

    for (int t = 0; t < NT; t++) {
        if (t + 1 < NT) CPA_WAIT(1);
        else            CPA_WAIT(0);
        __syncthreads();
        if (t + 2 < NT) issue(t + 2);

        const uint32_t sbase = sb + (t % 3) * GSTAGE;
#pragma unroll
        for (int ks = 0; ks < 4; ks++) {
            const uint32_t k0b = ks * 32;
            const uint32_t aB = sbase + (uint32_t)m0 * GSTR2 + k0b + laneA;
            const uint32_t bB = sbase + GPART + (uint32_t)n0 * GSTR2 + k0b + laneB4;

            uint32_t ah[4][4], bh[2][4];
#pragma unroll
            for (int mi = 0; mi < 4; mi++)
                LDSM_X4(ah[mi], aB + mi * 16 * GSTR2);
#pragma unroll
            for (int nj = 0; nj < 2; nj++)
                LDSM_X4(bh[nj], bB + nj * 16 * GSTR2);

#pragma unroll
            for (int mi = 0; mi < 4; mi++)
#pragma unroll
                for (int nj = 0; nj < 2; nj++) {
                    MMAH(c[mi][2 * nj],     ah[mi], (bh[nj] + 0));
                    MMAH(c[mi][2 * nj + 1], ah[mi], (bh[nj] + 2));
                }
        }
    }

    // ---- epilogue ----
    const int row_base = blockIdx.y * 128 + m0;
    const int col_base = blockIdx.x * 128 + n0;
#pragma unroll
    for (int mi = 0; mi < 4; mi++) {
#pragma unroll
        for (int ni = 0; ni < 4; ni++) {
            const int col = col_base + ni * 8 + 2 * tg;
            const float2 bv = *(const float2*)&bias[col];
#pragma unroll
            for (int half = 0; half < 2; half++) {
                const int row = row_base + mi * 16 + g + 8 * half;
                float e = c[mi][ni][2 * half]     + bv.x;
                float o = c[mi][ni][2 * half + 1] + bv.y;
                float o0 = e, o1 = o;
                if (SPLIT_OUT) {
                    if (col < 2 * D_) {   // RoPE on q and k
                        const int s = row & (S_ - 1);
                        const float2 cs = *(const float2*)&rot[s * HD_ + (col & (HD_ - 1))];
                        o0 = e * cs.x - o * cs.y;
                        o1 = e * cs.y + o * cs.x;
                    }
                    if (col < D_) {       // q: softmax scale * log2(e)
                        o0 *= QSCALE;
                        o1 *= QSCALE;
                    }
                    __half2 hv = __floats2half2_rn(o0, o1);
                    *(__half2*)&Ch[(size_t)row * N + col] = hv;
                } else {
                    float2 ov; ov.x = o0; ov.y = o1;
                    *(float2*)&C[(size_t)row * N + col] = ov;
                }
            }
        }
    }
}

// ---------------------------------------------------------------------------
// Tensor-core flash attention, fp16, exp2-domain softmax.
// CTA: 128 q rows, 8 warps x 16 rows. K sub-tiles of 64 keys, 4-stage ring
// (2 KV tiles of lookahead), one barrier per tile. 2 CTAs/SM.
// SMEM (fp16, stride 72): Q(128) | ring{K64,V64} x4
// ---------------------------------------------------------------------------
#define TSTR2   144
#define QB      (128 * TSTR2)             // 18432
#define KVST    (64 * TSTR2)              // 9216
#define STG     (2 * KVST)                // 18432 per stage
#define ATSMEM  (QB + 4 * STG)            // 92160

__global__ void __launch_bounds__(256, 2)
attn_mma(const __half* __restrict__ qkv, __half* __restrict__ oh)
{
    extern __shared__ __align__(16) char smem[];
    const uint32_t sb = smem_u32(smem);
    const int tid  = threadIdx.x;
    const int wid  = tid >> 5;
    const int lane = tid & 31;
    const int g    = lane >> 2;
    const int tg   = lane & 3;
    const int b    = blockIdx.z;
    const int h    = blockIdx.y;
    const int q0   = blockIdx.x * 128;

    // Q loader: 128 rows x 2 threads (part of commit group 0)
    {
        const int lrow = tid >> 1;
        const int lseg = (tid & 1) * 4;
        const size_t gq = ((size_t)(b * S_) + q0 + lrow) * (3 * D_) + h * HD_ + lseg * 8;
#pragma unroll
        for (int s = 0; s < 4; s++)
            CPA16(sb + (uint32_t)lrow * TSTR2 + (lseg + s) * 16, qkv + gq + s * 8);
    }

    // KV loader: 64 rows x 4 threads
    const int krow = tid >> 2;
    const int kseg = (tid & 3) * 2;
    auto issue_kv = [&](int t) {
        const size_t gk = ((size_t)(b * S_) + t * 64 + krow) * (3 * D_) + D_ + h * HD_ + kseg * 8;
        const uint32_t base = sb + QB + (t & 3) * STG + (uint32_t)krow * TSTR2 + kseg * 16;
        CPA16(base,             qkv + gk);
        CPA16(base + 16,        qkv + gk + 8);
        CPA16(base + KVST,      qkv + gk + D_);
        CPA16(base + KVST + 16, qkv + gk + D_ + 8);
        CPA_COMMIT();
    };

    issue_kv(0);   // group 0 (also contains Q)
    issue_kv(1);   // group 1
    issue_kv(2);   // group 2

    const uint32_t laneA  = (uint32_t)(lane & 15) * TSTR2 + (lane >> 4) * 16;
    const uint32_t laneB4 = (uint32_t)(lane & 7) * TSTR2 + ((lane >> 3) & 1) * 16
                          + (uint32_t)(lane >> 4) * 8 * TSTR2;
    const uint32_t laneV4 = (uint32_t)(lane & 15) * TSTR2 + (lane >> 4) * 16;

    const uint32_t aQ = sb + (uint32_t)(16 * wid) * TSTR2 + laneA;

    float o[8][4];
#pragma unroll
    for (int n = 0; n < 8; n++)
#pragma unroll
        for (int e = 0; e < 4; e++) o[n][e] = 0.0f;
    float mrow[2] = {-1e30f, -1e30f};
    float lsum[2] = {0.0f, 0.0f};

    uint32_t qf[4][4];

    const int NKT = S_ / 64;   // 32
    for (int t = 0; t < NKT; t++) {
        if (t + 2 < NKT)      CPA_WAIT(2);
        else if (t + 1 < NKT) CPA_WAIT(1);
        else                  CPA_WAIT(0);
        __syncthreads();
        if (t + 3 < NKT) issue_kv(t + 3);

        if (t == 0) {
#pragma unroll
            for (int ks = 0; ks < 4; ks++)
                LDSM_X4(qf[ks], aQ + ks * 32);
        }

        const uint32_t kb = sb + QB + (t & 3) * STG;

        // ---- scores: c[8][4] = Q(16 rows) . K^T(64 keys), log2 domain ----
        float c[8][4];
#pragma unroll
        for (int ni = 0; ni < 8; ni++)
#pragma unroll
            for (int e = 0; e < 4; e++) c[ni][e] = 0.0f;

#pragma unroll
        for (int ks = 0; ks < 4; ks++) {
#pragma unroll
            for (int nj = 0; nj < 4; nj++) {
                uint32_t bh[4];
                LDSM_X4(bh, kb + (uint32_t)(nj * 16) * TSTR2 + ks * 32 + laneB4);
                MMAH(c[2 * nj],     qf[ks], (bh + 0));
                MMAH(c[2 * nj + 1], qf[ks], (bh + 2));
            }
        }

        // ---- online softmax in exp2 domain ----
        float tmax0 = -1e30f, tmax1 = -1e30f;
#pragma unroll
        for (int ni = 0; ni < 8; ni++) {
            tmax0 = fmaxf(tmax0, fmaxf(c[ni][0], c[ni][1]));
            tmax1 = fmaxf(tmax1, fmaxf(c[ni][2], c[ni][3]));
        }
        tmax0 = fmaxf(tmax0, __shfl_xor_sync(0xffffffffu, tmax0, 1));
        tmax0 = fmaxf(tmax0, __shfl_xor_sync(0xffffffffu, tmax0, 2));
        tmax1 = fmaxf(tmax1, __shfl_xor_sync(0xffffffffu, tmax1, 1));
        tmax1 = fmaxf(tmax1, __shfl_xor_sync(0xffffffffu, tmax1, 2));

        const float mn0 = fmaxf(mrow[0], tmax0);
        const float mn1 = fmaxf(mrow[1], tmax1);
        const float al0 = exp2f(mrow[0] - mn0);
        const float al1 = exp2f(mrow[1] - mn1);
        mrow[0] = mn0;
        mrow[1] = mn1;

        float s0 = 0.0f, s1 = 0.0f;
#pragma unroll
        for (int ni = 0; ni < 8; ni++) {
            c[ni][0] = exp2f(c[ni][0] - mn0);
            c[ni][1] = exp2f(c[ni][1] - mn0);
            c[ni][2] = exp2f(c[ni][2] - mn1);
            c[ni][3] = exp2f(c[ni][3] - mn1);
            s0 += c[ni][0] + c[ni][1];
            s1 += c[ni][2] + c[ni][3];
        }
        s0 += __shfl_xor_sync(0xffffffffu, s0, 1);
        s0 += __shfl_xor_sync(0xffffffffu, s0, 2);
        s1 += __shfl_xor_sync(0xffffffffu, s1, 1);
        s1 += __shfl_xor_sync(0xffffffffu, s1, 2);
        lsum[0] = lsum[0] * al0 + s0;
        lsum[1] = lsum[1] * al1 + s1;

#pragma unroll
        for (int n = 0; n < 8; n++) {
            o[n][0] *= al0; o[n][1] *= al0;
            o[n][2] *= al1; o[n][3] *= al1;
        }

        // ---- PV: o += P(16x64) . V(64x64), P rounded to fp16 ----
        const uint32_t vbb = kb + KVST;
#pragma unroll
        for (int kj = 0; kj < 4; kj++) {
            uint32_t ap[4];
            {
                __half2 p0 = __floats2half2_rn(c[2 * kj][0],     c[2 * kj][1]);
                __half2 p1 = __floats2half2_rn(c[2 * kj][2],     c[2 * kj][3]);
                __half2 p2 = __floats2half2_rn(c[2 * kj + 1][0], c[2 * kj + 1][1]);
                __half2 p3 = __floats2half2_rn(c[2 * kj + 1][2], c[2 * kj + 1][3]);
                ap[0] = *(uint32_t*)&p0;
                ap[1] = *(uint32_t*)&p1;
                ap[2] = *(uint32_t*)&p2;
                ap[3] = *(uint32_t*)&p3;
            }
#pragma unroll
            for (int np = 0; np < 4; np++) {
                uint32_t vh[4];
                LDSM_X4T(vh, vbb + (uint32_t)(16 * kj) * TSTR2 + np * 32 + laneV4);
                MMAH(o[2 * np],     ap, (vh + 0));
                MMAH(o[2 * np + 1], ap, (vh + 2));
            }
        }
    }

    // ---- epilogue: normalize, round to fp16 ----
    const float inv0 = 1.0f / lsum[0];
    const float inv1 = 1.0f / lsum[1];
    const int r0 = b * S_ + q0 + 16 * wid + g;
    const int cb = h * HD_ + 2 * tg;
#pragma unroll
    for (int n = 0; n < 8; n++) {
        const int col = cb + 8 * n;
        __half2 hv = __floats2half2_rn(o[n][0] * inv0, o[n][1] * inv0);
        *(__half2*)&oh[(size_t)r0 * D_ + col] = hv;
        hv = __floats2half2_rn(o[n][2] * inv1, o[n][3] * inv1);
        *(__half2*)&oh[(size_t)(r0 + 8) * D_ + col] = hv;
    }
}

// ---------------------------------------------------------------------------
extern "C" void kernel_launch(void* const* d_in, const int* in_sizes, int n_in,
                              void* d_out, int out_size)
{
    const float* x     = (const float*)d_in[0];
    const float* rot   = (const float*)d_in[1];
    const float* w_qkv = (const float*)d_in[2];
    const float* b_qkv = (const float*)d_in[3];
    const float* w_o   = (const float*)d_in[4];
    const float* b_o   = (const float*)d_in[5];
    float* out = (float*)d_out;

    __half *xh, *wh, *woh, *qkv, *ah;
    cudaGetSymbolAddress((void**)&xh,  g_xh);
    cudaGetSymbolAddress((void**)&wh,  g_wh);
    cudaGetSymbolAddress((void**)&woh, g_woh);
    cudaGetSymbolAddress((void**)&qkv, g_qkv);
    cudaGetSymbolAddress((void**)&ah,  g_ah);

    static bool attr_set = false;
    if (!attr_set) {
        cudaFuncSetAttribute(gemm_mma<true>,
                             cudaFuncAttributeMaxDynamicSharedMemorySize, GSMEM);
        cudaFuncSetAttribute(gemm_mma<false>,
                             cudaFuncAttributeMaxDynamicSharedMemorySize, GSMEM);
        cudaFuncSetAttribute(attn_mma,
                             cudaFuncAttributeMaxDynamicSharedMemorySize, ATSMEM);
        attr_set = true;
    }

    // ---- prep: round x and weights to fp16 (single fused launch) ----
    prep_kernel<<<(N4_ALL + 255) / 256, 256>>>(
        (const float4*)x, (const float4*)w_qkv, (const float4*)w_o,
        (__half2*)xh, (__half2*)wh, (__half2*)woh);

    // ---- 1) QKV projection + bias + RoPE + q-scale(log2e) -> fp16 ----
    {
        dim3 grid((3 * D_) / 128, M_ / 128);
        gemm_mma<true><<<grid, 256, GSMEM>>>(xh, wh, b_qkv, rot,
                                             nullptr, qkv, M_, 3 * D_, D_);
    }

    // ---- 2) Tensor-core flash attention -> fp16 ----
    {
        dim3 grid(S_ / 128, H_, B_);
        attn_mma<<<grid, 256, ATSMEM>>>(qkv, ah);
    }

    // ---- 3) Output projection + bias -> fp32 out ----
    {
        dim3 grid(D_ / 128, M_ / 128);
        gemm_mma<false><<<grid, 256, GSMEM>>>(ah, woh, b_o, nullptr,
                                              out, nullptr, M_, D_, D_);
    }
    (void)in_sizes; (void)n_in; (void)out_size;
}

// round 12
// speedup vs baseline: 1.0250x; 1.0250x over previous
#include <cuda_runtime.h>
#include <cuda_fp16.h>
#include <cstdint>

#define B_  2
#define S_  2048
#define D_  1024
#define H_  16
#define HD_ 64
#define M_  (B_ * S_)   // 4096

// ---------------- device scratch (no cudaMalloc allowed) ----------------
__device__ __half g_xh[(size_t)M_ * D_];           // x rounded
__device__ __half g_wh[(size_t)3 * D_ * D_];       // w_qkv rounded
__device__ __half g_woh[(size_t)D_ * D_];          // w_o rounded
__device__ __half g_qkv[(size_t)M_ * 3 * D_];      // qkv fp16 (q pre-scaled by 0.125*log2e)
__device__ __half g_ah[(size_t)M_ * D_];           // attn out fp16

// ---------------- PTX helpers (sm_80+ portable) ----------------
__device__ __forceinline__ uint32_t smem_u32(const void* p) {
    uint32_t a;
    asm("{ .reg .u64 t; cvta.to.shared.u64 t, %1; cvt.u32.u64 %0, t; }"
        : "=r"(a) : "l"(p));
    return a;
}

#define CPA16(saddr, gptr) \
    asm volatile("cp.async.cg.shared.global [%0], [%1], 16;" \
                 :: "r"(saddr), "l"(gptr) : "memory")
#define CPA_COMMIT() asm volatile("cp.async.commit_group;" ::: "memory")
#define CPA_WAIT(n)  asm volatile("cp.async.wait_group %0;" :: "n"(n) : "memory")

#define LDSM_X4(r, addr) \
    asm volatile("ldmatrix.sync.aligned.m8n8.x4.shared.b16 {%0,%1,%2,%3}, [%4];" \
                 : "=r"((r)[0]), "=r"((r)[1]), "=r"((r)[2]), "=r"((r)[3]) \
                 : "r"(addr))
#define LDSM_X4T(r, addr) \
    asm volatile("ldmatrix.sync.aligned.m8n8.x4.trans.shared.b16 {%0,%1,%2,%3}, [%4];" \
                 : "=r"((r)[0]), "=r"((r)[1]), "=r"((r)[2]), "=r"((r)[3]) \
                 : "r"(addr))

#define MMAH(c, a, b) \
    asm volatile("mma.sync.aligned.m16n8k16.row.col.f32.f16.f16.f32 " \
                 "{%0,%1,%2,%3}, {%4,%5,%6,%7}, {%8,%9}, {%0,%1,%2,%3};" \
                 : "+f"((c)[0]), "+f"((c)[1]), "+f"((c)[2]), "+f"((c)[3]) \
                 : "r"((a)[0]), "r"((a)[1]), "r"((a)[2]), "r"((a)[3]), \
                   "r"((b)[0]), "r"((b)[1]))

// ---------------------------------------------------------------------------
// fused prep: round x, w_qkv, w_o to fp16 in one grid-stride launch
// ---------------------------------------------------------------------------
#define N4_X   (M_ * D_ / 4)
#define N4_W   (3 * D_ * D_ / 4)
#define N4_WO  (D_ * D_ / 4)
#define N4_ALL (N4_X + N4_W + N4_WO)

__global__ void __launch_bounds__(256)
prep_kernel(const float4* __restrict__ x, const float4* __restrict__ w,
            const float4* __restrict__ wo, __half2* __restrict__ xh,
            __half2* __restrict__ wh, __half2* __restrict__ woh)
{
    int i = blockIdx.x * 256 + threadIdx.x;
    if (i >= N4_ALL) return;
    const float4* src;
    __half2* dst;
    int j;
    if (i < N4_X)            { src = x;  dst = xh;  j = i; }
    else if (i < N4_X + N4_W){ src = w;  dst = wh;  j = i - N4_X; }
    else                     { src = wo; dst = woh; j = i - N4_X - N4_W; }
    float4 v = src[j];
    dst[2 * j]     = __floats2half2_rn(v.x, v.y);
    dst[2 * j + 1] = __floats2half2_rn(v.z, v.w);
}

// ---------------------------------------------------------------------------
// Tensor-core GEMM, fp16: C = Ah[M,K] @ Bh[N,K]^T + bias.
// SPLIT_OUT: +RoPE (+0.125*log2e q scale), writes fp16. Else fp32 + bias.
// 128x128 CTA tile, 8 warps (2m x 4n), BK=32, 5-stage cp.async pipeline
// with correct wait -> sync -> issue ordering (wait_group is per-thread;
// the barrier AFTER the wait is what publishes other threads' tiles).
// ---------------------------------------------------------------------------
#define BKC      32
#define ASTRIDE  40
#define STR2     (ASTRIDE * 2)
#define APART    (128 * STR2)           // 10240 B
#define STAGE    (2 * APART)            // Ah, Bh = 20480 B
#define NSTG     5
#define GSMEM    (NSTG * STAGE)         // 102400 B (2 CTA/SM = 200 KB, fits)

#define QSCALE   0.18033688011112042f   // 0.125 * log2(e)

template <bool SPLIT_OUT>
__global__ void __launch_bounds__(256, 2)
gemm_mma(const __half* __restrict__ Ah, const __half* __restrict__ Bh,
         const float* __restrict__ bias, const float* __restrict__ rot,
         float* __restrict__ C, __half* __restrict__ Ch, int M, int N, int K)
{
    extern __shared__ __align__(16) char smem[];
    const uint32_t sb = smem_u32(smem);

    const int tid  = threadIdx.x;
    const int wid  = tid >> 5;
    const int lane = tid & 31;
    const int g    = lane >> 2;
    const int tg   = lane & 3;
    const int m0   = (wid & 1) * 64;
    const int n0   = (wid >> 1) * 32;

    const int lrow = tid >> 1;
    const int cseg = (tid & 1) * 16;
    const uint32_t so = (uint32_t)lrow * STR2 + cseg * 2;

    const size_t rA = (size_t)(blockIdx.y * 128 + lrow) * K + cseg;
    const size_t rB = (size_t)(blockIdx.x * 128 + lrow) * K + cseg;
    const __half* pAh = Ah + rA;
    const __half* pBh = Bh + rB;

    const uint32_t laneA  = (uint32_t)(lane & 15) * STR2 + (lane >> 4) * 16;
    const uint32_t laneB4 = (uint32_t)(lane & 7) * STR2 + ((lane >> 3) & 1) * 16
                          + (uint32_t)(lane >> 4) * 8 * STR2;

    float c[4][4][4];
#pragma unroll
    for (int mi = 0; mi < 4; mi++)
#pragma unroll
        for (int ni = 0; ni < 4; ni++)
#pragma unroll
            for (int e = 0; e < 4; e++) c[mi][ni][e] = 0.0f;

    const int NT = K / BKC;   // 32

    auto issue = [&](int t) {
        const uint32_t sbase = sb + (t % NSTG) * STAGE;
        const size_t k0 = (size_t)t * BKC;
        CPA16(sbase + so,              pAh + k0);
        CPA16(sbase + so + 16,         pAh + k0 + 8);
        CPA16(sbase + APART + so,      pBh + k0);
        CPA16(sbase + APART + so + 16, pBh + k0 + 8);
        CPA_COMMIT();
    };

    issue(0);
    issue(1);
    issue(2);
    issue(3);

    for (int t = 0; t < NT; t++) {
        if (t + 3 < NT)      CPA_WAIT(3);
        else if (t + 2 < NT) CPA_WAIT(2);
        else if (t + 1 < NT) CPA_WAIT(1);
        else                 CPA_WAIT(0);
        __syncthreads();                 // publish all threads' group-t tiles
        if (t + 4 < NT) issue(t + 4);    // writes stage (t-1)%5, safe post-sync

        const uint32_t sbase = sb + (t % NSTG) * STAGE;
#pragma unroll
        for (int ks = 0; ks < 2; ks++) {
            const uint32_t k0b = ks * 32;
            const uint32_t aB = sbase + (uint32_t)m0 * STR2 + k0b + laneA;
            const uint32_t bB = sbase + APART + (uint32_t)n0 * STR2 + k0b + laneB4;

            uint32_t ah[4][4], bh[2][4];
#pragma unroll
            for (int mi = 0; mi < 4; mi++)
                LDSM_X4(ah[mi], aB + mi * 16 * STR2);
#pragma unroll
            for (int nj = 0; nj < 2; nj++)
                LDSM_X4(bh[nj], bB + nj * 16 * STR2);

#pragma unroll
            for (int mi = 0; mi < 4; mi++)
#pragma unroll
                for (int nj = 0; nj < 2; nj++) {
                    MMAH(c[mi][2 * nj],     ah[mi], (bh[nj] + 0));
                    MMAH(c[mi][2 * nj + 1], ah[mi], (bh[nj] + 2));
                }
        }
    }

    // ---- epilogue ----
    const int row_base = blockIdx.y * 128 + m0;
    const int col_base = blockIdx.x * 128 + n0;
#pragma unroll
    for (int mi = 0; mi < 4; mi++) {
#pragma unroll
        for (int ni = 0; ni < 4; ni++) {
            const int col = col_base + ni * 8 + 2 * tg;
            const float2 bv = *(const float2*)&bias[col];
#pragma unroll
            for (int half = 0; half < 2; half++) {
                const int row = row_base + mi * 16 + g + 8 * half;
                float e = c[mi][ni][2 * half]     + bv.x;
                float o = c[mi][ni][2 * half + 1] + bv.y;
                float o0 = e, o1 = o;
                if (SPLIT_OUT) {
                    if (col < 2 * D_) {   // RoPE on q and k
                        const int s = row & (S_ - 1);
                        const float2 cs = *(const float2*)&rot[s * HD_ + (col & (HD_ - 1))];
                        o0 = e * cs.x - o * cs.y;
                        o1 = e * cs.y + o * cs.x;
                    }
                    if (col < D_) {       // q: softmax scale * log2(e)
                        o0 *= QSCALE;
                        o1 *= QSCALE;
                    }
                    __half2 hv = __floats2half2_rn(o0, o1);
                    *(__half2*)&Ch[(size_t)row * N + col] = hv;
                } else {
                    float2 ov; ov.x = o0; ov.y = o1;
                    *(float2*)&C[(size_t)row * N + col] = ov;
                }
            }
        }
    }
}

// ---------------------------------------------------------------------------
// Tensor-core flash attention, fp16, exp2-domain softmax. (R9-proven)
// CTA: 128 q rows, 8 warps x 16 rows. K sub-tiles of 64 keys, 4-stage ring,
// wait -> sync -> issue ordering, one barrier per tile. 2 CTAs/SM.
// SMEM (fp16, stride 72): Q(128) | ring{K64,V64} x4
// ---------------------------------------------------------------------------
#define TSTR2   144
#define QB      (128 * TSTR2)             // 18432
#define KVST    (64 * TSTR2)              // 9216
#define STG     (2 * KVST)                // 18432 per stage
#define ATSMEM  (QB + 4 * STG)            // 92160

__global__ void __launch_bounds__(256, 2)
attn_mma(const __half* __restrict__ qkv, __half* __restrict__ oh)
{
    extern __shared__ __align__(16) char smem[];
    const uint32_t sb = smem_u32(smem);
    const int tid  = threadIdx.x;
    const int wid  = tid >> 5;
    const int lane = tid & 31;
    const int g    = lane >> 2;
    const int tg   = lane & 3;
    const int b    = blockIdx.z;
    const int h    = blockIdx.y;
    const int q0   = blockIdx.x * 128;

    // Q loader: 128 rows x 2 threads (part of commit group 0)
    {
        const int lrow = tid >> 1;
        const int lseg = (tid & 1) * 4;
        const size_t gq = ((size_t)(b * S_) + q0 + lrow) * (3 * D_) + h * HD_ + lseg * 8;
#pragma unroll
        for (int s = 0; s < 4; s++)
            CPA16(sb + (uint32_t)lrow * TSTR2 + (lseg + s) * 16, qkv + gq + s * 8);
    }

    // KV loader: 64 rows x 4 threads
    const int krow = tid >> 2;
    const int kseg = (tid & 3) * 2;
    auto issue_kv = [&](int t) {
        const size_t gk = ((size_t)(b * S_) + t * 64 + krow) * (3 * D_) + D_ + h * HD_ + kseg * 8;
        const uint32_t base = sb + QB + (t & 3) * STG + (uint32_t)krow * TSTR2 + kseg * 16;
        CPA16(base,             qkv + gk);
        CPA16(base + 16,        qkv + gk + 8);
        CPA16(base + KVST,      qkv + gk + D_);
        CPA16(base + KVST + 16, qkv + gk + D_ + 8);
        CPA_COMMIT();
    };

    issue_kv(0);   // group 0 (also contains Q)
    issue_kv(1);   // group 1
    issue_kv(2);   // group 2

    const uint32_t laneA  = (uint32_t)(lane & 15) * TSTR2 + (lane >> 4) * 16;
    const uint32_t laneB4 = (uint32_t)(lane & 7) * TSTR2 + ((lane >> 3) & 1) * 16
                          + (uint32_t)(lane >> 4) * 8 * TSTR2;
    const uint32_t laneV4 = (uint32_t)(lane & 15) * TSTR2 + (lane >> 4) * 16;

    const uint32_t aQ = sb + (uint32_t)(16 * wid) * TSTR2 + laneA;

    float o[8][4];
#pragma unroll
    for (int n = 0; n < 8; n++)
#pragma unroll
        for (int e = 0; e < 4; e++) o[n][e] = 0.0f;
    float mrow[2] = {-1e30f, -1e30f};
    float lsum[2] = {0.0f, 0.0f};

    uint32_t qf[4][4];

    const int NKT = S_ / 64;   // 32
    for (int t = 0; t < NKT; t++) {
        if (t + 2 < NKT)      CPA_WAIT(2);
        else if (t + 1 < NKT) CPA_WAIT(1);
        else                  CPA_WAIT(0);
        __syncthreads();
        if (t + 3 < NKT) issue_kv(t + 3);

        if (t == 0) {
#pragma unroll
            for (int ks = 0; ks < 4; ks++)
                LDSM_X4(qf[ks], aQ + ks * 32);
        }

        const uint32_t kb = sb + QB + (t & 3) * STG;

        // ---- scores: c[8][4] = Q(16 rows) . K^T(64 keys), log2 domain ----
        float c[8][4];
#pragma unroll
        for (int ni = 0; ni < 8; ni++)
#pragma unroll
            for (int e = 0; e < 4; e++) c[ni][e] = 0.0f;

#pragma unroll
        for (int ks = 0; ks < 4; ks++) {
#pragma unroll
            for (int nj = 0; nj < 4; nj++) {
                uint32_t bh[4];
                LDSM_X4(bh, kb + (uint32_t)(nj * 16) * TSTR2 + ks * 32 + laneB4);
                MMAH(c[2 * nj],     qf[ks], (bh + 0));
                MMAH(c[2 * nj + 1], qf[ks], (bh + 2));
            }
        }

        // ---- online softmax in exp2 domain ----
        float tmax0 = -1e30f, tmax1 = -1e30f;
#pragma unroll
        for (int ni = 0; ni < 8; ni++) {
            tmax0 = fmaxf(tmax0, fmaxf(c[ni][0], c[ni][1]));
            tmax1 = fmaxf(tmax1, fmaxf(c[ni][2], c[ni][3]));
        }
        tmax0 = fmaxf(tmax0, __shfl_xor_sync(0xffffffffu, tmax0, 1));
        tmax0 = fmaxf(tmax0, __shfl_xor_sync(0xffffffffu, tmax0, 2));
        tmax1 = fmaxf(tmax1, __shfl_xor_sync(0xffffffffu, tmax1, 1));
        tmax1 = fmaxf(tmax1, __shfl_xor_sync(0xffffffffu, tmax1, 2));

        const float mn0 = fmaxf(mrow[0], tmax0);
        const float mn1 = fmaxf(mrow[1], tmax1);
        const float al0 = exp2f(mrow[0] - mn0);
        const float al1 = exp2f(mrow[1] - mn1);
        mrow[0] = mn0;
        mrow[1] = mn1;

        float s0 = 0.0f, s1 = 0.0f;
#pragma unroll
        for (int ni = 0; ni < 8; ni++) {
            c[ni][0] = exp2f(c[ni][0] - mn0);
            c[ni][1] = exp2f(c[ni][1] - mn0);
            c[ni][2] = exp2f(c[ni][2] - mn1);
            c[ni][3] = exp2f(c[ni][3] - mn1);
            s0 += c[ni][0] + c[ni][1];
            s1 += c[ni][2] + c[ni][3];
        }
        s0 += __shfl_xor_sync(0xffffffffu, s0, 1);
        s0 += __shfl_xor_sync(0xffffffffu, s0, 2);
        s1 += __shfl_xor_sync(0xffffffffu, s1, 1);
        s1 += __shfl_xor_sync(0xffffffffu, s1, 2);
        lsum[0] = lsum[0] * al0 + s0;
        lsum[1] = lsum[1] * al1 + s1;

#pragma unroll
        for (int n = 0; n < 8; n++) {
            o[n][0] *= al0; o[n][1] *= al0;
            o[n][2] *= al1; o[n][3] *= al1;
        }

        // ---- PV: o += P(16x64) . V(64x64), P rounded to fp16 ----
        const uint32_t vbb = kb + KVST;
#pragma unroll
        for (int kj = 0; kj < 4; kj++) {
            uint32_t ap[4];
            {
                __half2 p0 = __floats2half2_rn(c[2 * kj][0],     c[2 * kj][1]);
                __half2 p1 = __floats2half2_rn(c[2 * kj][2],     c[2 * kj][3]);
                __half2 p2 = __floats2half2_rn(c[2 * kj + 1][0], c[2 * kj + 1][1]);
                __half2 p3 = __floats2half2_rn(c[2 * kj + 1][2], c[2 * kj + 1][3]);
                ap[0] = *(uint32_t*)&p0;
                ap[1] = *(uint32_t*)&p1;
                ap[2] = *(uint32_t*)&p2;
                ap[3] = *(uint32_t*)&p3;
            }
#pragma unroll
            for (int np = 0; np < 4; np++) {
                uint32_t vh[4];
                LDSM_X4T(vh, vbb + (uint32_t)(16 * kj) * TSTR2 + np * 32 + laneV4);
                MMAH(o[2 * np],     ap, (vh + 0));
                MMAH(o[2 * np + 1], ap, (vh + 2));
            }
        }
    }

    // ---- epilogue: normalize, round to fp16 ----
    const float inv0 = 1.0f / lsum[0];
    const float inv1 = 1.0f / lsum[1];
    const int r0 = b * S_ + q0 + 16 * wid + g;
    const int cb = h * HD_ + 2 * tg;
#pragma unroll
    for (int n = 0; n < 8; n++) {
        const int col = cb + 8 * n;
        __half2 hv = __floats2half2_rn(o[n][0] * inv0, o[n][1] * inv0);
        *(__half2*)&oh[(size_t)r0 * D_ + col] = hv;
        hv = __floats2half2_rn(o[n][2] * inv1, o[n][3] * inv1);
        *(__half2*)&oh[(size_t)(r0 + 8) * D_ + col] = hv;
    }
}

// ---------------------------------------------------------------------------
extern "C" void kernel_launch(void* const* d_in, const int* in_sizes, int n_in,
                              void* d_out, int out_size)
{
    const float* x     = (const float*)d_in[0];
    const float* rot   = (const float*)d_in[1];
    const float* w_qkv = (const float*)d_in[2];
    const float* b_qkv = (const float*)d_in[3];
    const float* w_o   = (const float*)d_in[4];
    const float* b_o   = (const float*)d_in[5];
    float* out = (float*)d_out;

    __half *xh, *wh, *woh, *qkv, *ah;
    cudaGetSymbolAddress((void**)&xh,  g_xh);
    cudaGetSymbolAddress((void**)&wh,  g_wh);
    cudaGetSymbolAddress((void**)&woh, g_woh);
    cudaGetSymbolAddress((void**)&qkv, g_qkv);
    cudaGetSymbolAddress((void**)&ah,  g_ah);

    static bool attr_set = false;
    if (!attr_set) {
        cudaFuncSetAttribute(gemm_mma<true>,
                             cudaFuncAttributeMaxDynamicSharedMemorySize, GSMEM);
        cudaFuncSetAttribute(gemm_mma<false>,
                             cudaFuncAttributeMaxDynamicSharedMemorySize, GSMEM);
        cudaFuncSetAttribute(attn_mma,
                             cudaFuncAttributeMaxDynamicSharedMemorySize, ATSMEM);
        attr_set = true;
    }

    // ---- prep: round x and weights to fp16 (single fused launch) ----
    prep_kernel<<<(N4_ALL + 255) / 256, 256>>>(
        (const float4*)x, (const float4*)w_qkv, (const float4*)w_o,
        (__half2*)xh, (__half2*)wh, (__half2*)woh);

    // ---- 1) QKV projection + bias + RoPE + q-scale(log2e) -> fp16 ----
    {
        dim3 grid((3 * D_) / 128, M_ / 128);
        gemm_mma<true><<<grid, 256, GSMEM>>>(xh, wh, b_qkv, rot,
                                             nullptr, qkv, M_, 3 * D_, D_);
    }

    // ---- 2) Tensor-core flash attention -> fp16 ----
    {
        dim3 grid(S_ / 128, H_, B_);
        attn_mma<<<grid, 256, ATSMEM>>>(qkv, ah);
    }

    // ---- 3) Output projection + bias -> fp32 out ----
    {
        dim3 grid(D_ / 128, M_ / 128);
        gemm_mma<false><<<grid, 256, GSMEM>>>(ah, woh, b_o, nullptr,
                                              out, nullptr, M_, D_, D_);
    }
    (void)in_sizes; (void)n_in; (void)out_size;
}

// round 13
// speedup vs baseline: 1.0391x; 1.0138x over previous
#include <cuda_runtime.h>
#include <cuda_fp16.h>
#include <cstdint>

#define B_  2
#define S_  2048
#define D_  1024
#define H_  16
#define HD_ 64
#define M_  (B_ * S_)   // 4096

// ---------------- device scratch (no cudaMalloc allowed) ----------------
__device__ __half g_xh[(size_t)M_ * D_];           // x rounded
__device__ __half g_wh[(size_t)3 * D_ * D_];       // w_qkv rounded
__device__ __half g_woh[(size_t)D_ * D_];          // w_o rounded
__device__ __half g_qkv[(size_t)M_ * 3 * D_];      // qkv fp16 (q pre-scaled by 0.125*log2e)
__device__ __half g_ah[(size_t)M_ * D_];           // attn out fp16

// ---------------- PTX helpers (sm_80+ portable) ----------------
__device__ __forceinline__ uint32_t smem_u32(const void* p) {
    uint32_t a;
    asm("{ .reg .u64 t; cvta.to.shared.u64 t, %1; cvt.u32.u64 %0, t; }"
        : "=r"(a) : "l"(p));
    return a;
}

#define CPA16(saddr, gptr) \
    asm volatile("cp.async.cg.shared.global [%0], [%1], 16;" \
                 :: "r"(saddr), "l"(gptr) : "memory")
#define CPA_COMMIT() asm volatile("cp.async.commit_group;" ::: "memory")
#define CPA_WAIT(n)  asm volatile("cp.async.wait_group %0;" :: "n"(n) : "memory")

#define LDSM_X4(r, addr) \
    asm volatile("ldmatrix.sync.aligned.m8n8.x4.shared.b16 {%0,%1,%2,%3}, [%4];" \
                 : "=r"((r)[0]), "=r"((r)[1]), "=r"((r)[2]), "=r"((r)[3]) \
                 : "r"(addr))
#define LDSM_X4T(r, addr) \
    asm volatile("ldmatrix.sync.aligned.m8n8.x4.trans.shared.b16 {%0,%1,%2,%3}, [%4];" \
                 : "=r"((r)[0]), "=r"((r)[1]), "=r"((r)[2]), "=r"((r)[3]) \
                 : "r"(addr))

#define MMAH(c, a, b) \
    asm volatile("mma.sync.aligned.m16n8k16.row.col.f32.f16.f16.f32 " \
                 "{%0,%1,%2,%3}, {%4,%5,%6,%7}, {%8,%9}, {%0,%1,%2,%3};" \
                 : "+f"((c)[0]), "+f"((c)[1]), "+f"((c)[2]), "+f"((c)[3]) \
                 : "r"((a)[0]), "r"((a)[1]), "r"((a)[2]), "r"((a)[3]), \
                   "r"((b)[0]), "r"((b)[1]))

// ---------------------------------------------------------------------------
// fused prep: round x, w_qkv, w_o to fp16 in one grid-stride launch
// ---------------------------------------------------------------------------
#define N4_X   (M_ * D_ / 4)
#define N4_W   (3 * D_ * D_ / 4)
#define N4_WO  (D_ * D_ / 4)
#define N4_ALL (N4_X + N4_W + N4_WO)

__global__ void __launch_bounds__(256)
prep_kernel(const float4* __restrict__ x, const float4* __restrict__ w,
            const float4* __restrict__ wo, __half2* __restrict__ xh,
            __half2* __restrict__ wh, __half2* __restrict__ woh)
{
    int i = blockIdx.x * 256 + threadIdx.x;
    if (i >= N4_ALL) return;
    const float4* src;
    __half2* dst;
    int j;
    if (i < N4_X)            { src = x;  dst = xh;  j = i; }
    else if (i < N4_X + N4_W){ src = w;  dst = wh;  j = i - N4_X; }
    else                     { src = wo; dst = woh; j = i - N4_X - N4_W; }
    float4 v = src[j];
    dst[2 * j]     = __floats2half2_rn(v.x, v.y);
    dst[2 * j + 1] = __floats2half2_rn(v.z, v.w);
}

// ---------------------------------------------------------------------------
// Tensor-core GEMM, fp16: C = Ah[M,K] @ Bh[N,K]^T + bias.
// SPLIT_OUT: +RoPE (+0.125*log2e q scale), writes fp16. Else fp32 + bias.
// 128x128 CTA tile, 8 warps (2m x 4n), BK=32, 4-stage cp.async pipeline,
// graduated wait -> sync -> issue (R9-proven ordering).
// ---------------------------------------------------------------------------
#define BKC      32
#define ASTRIDE  40
#define STR2     (ASTRIDE * 2)
#define APART    (128 * STR2)           // 10240 B
#define STAGE    (2 * APART)            // Ah, Bh
#define GSMEM    (4 * STAGE)            // 81920 B

#define QSCALE   0.18033688011112042f   // 0.125 * log2(e)

template <bool SPLIT_OUT>
__global__ void __launch_bounds__(256, 2)
gemm_mma(const __half* __restrict__ Ah, const __half* __restrict__ Bh,
         const float* __restrict__ bias, const float* __restrict__ rot,
         float* __restrict__ C, __half* __restrict__ Ch, int M, int N, int K)
{
    extern __shared__ __align__(16) char smem[];
    const uint32_t sb = smem_u32(smem);

    const int tid  = threadIdx.x;
    const int wid  = tid >> 5;
    const int lane = tid & 31;
    const int g    = lane >> 2;
    const int tg   = lane & 3;
    const int m0   = (wid & 1) * 64;
    const int n0   = (wid >> 1) * 32;

    const int lrow = tid >> 1;
    const int cseg = (tid & 1) * 16;
    const uint32_t so = (uint32_t)lrow * STR2 + cseg * 2;

    const size_t rA = (size_t)(blockIdx.y * 128 + lrow) * K + cseg;
    const size_t rB = (size_t)(blockIdx.x * 128 + lrow) * K + cseg;
    const __half* pAh = Ah + rA;
    const __half* pBh = Bh + rB;

    const uint32_t laneA  = (uint32_t)(lane & 15) * STR2 + (lane >> 4) * 16;
    const uint32_t laneB4 = (uint32_t)(lane & 7) * STR2 + ((lane >> 3) & 1) * 16
                          + (uint32_t)(lane >> 4) * 8 * STR2;

    float c[4][4][4];
#pragma unroll
    for (int mi = 0; mi < 4; mi++)
#pragma unroll
        for (int ni = 0; ni < 4; ni++)
#pragma unroll
            for (int e = 0; e < 4; e++) c[mi][ni][e] = 0.0f;

    const int NT = K / BKC;   // 32

    auto issue = [&](int t) {
        const uint32_t sbase = sb + (t & 3) * STAGE;
        const size_t k0 = (size_t)t * BKC;
        CPA16(sbase + so,              pAh + k0);
        CPA16(sbase + so + 16,         pAh + k0 + 8);
        CPA16(sbase + APART + so,      pBh + k0);
        CPA16(sbase + APART + so + 16, pBh + k0 + 8);
        CPA_COMMIT();
    };

    issue(0);
    issue(1);
    issue(2);

    for (int t = 0; t < NT; t++) {
        if (t + 2 < NT)      CPA_WAIT(2);
        else if (t + 1 < NT) CPA_WAIT(1);
        else                 CPA_WAIT(0);
        __syncthreads();
        if (t + 3 < NT) issue(t + 3);

        const uint32_t sbase = sb + (t & 3) * STAGE;
#pragma unroll
        for (int ks = 0; ks < 2; ks++) {
            const uint32_t k0b = ks * 32;
            const uint32_t aB = sbase + (uint32_t)m0 * STR2 + k0b + laneA;
            const uint32_t bB = sbase + APART + (uint32_t)n0 * STR2 + k0b + laneB4;

            uint32_t ah[4][4], bh[2][4];
#pragma unroll
            for (int mi = 0; mi < 4; mi++)
                LDSM_X4(ah[mi], aB + mi * 16 * STR2);
#pragma unroll
            for (int nj = 0; nj < 2; nj++)
                LDSM_X4(bh[nj], bB + nj * 16 * STR2);

#pragma unroll
            for (int mi = 0; mi < 4; mi++)
#pragma unroll
                for (int nj = 0; nj < 2; nj++) {
                    MMAH(c[mi][2 * nj],     ah[mi], (bh[nj] + 0));
                    MMAH(c[mi][2 * nj + 1], ah[mi], (bh[nj] + 2));
                }
        }
    }

    // ---- epilogue ----
    const int row_base = blockIdx.y * 128 + m0;
    const int col_base = blockIdx.x * 128 + n0;
#pragma unroll
    for (int mi = 0; mi < 4; mi++) {
#pragma unroll
        for (int ni = 0; ni < 4; ni++) {
            const int col = col_base + ni * 8 + 2 * tg;
            const float2 bv = *(const float2*)&bias[col];
#pragma unroll
            for (int half = 0; half < 2; half++) {
                const int row = row_base + mi * 16 + g + 8 * half;
                float e = c[mi][ni][2 * half]     + bv.x;
                float o = c[mi][ni][2 * half + 1] + bv.y;
                float o0 = e, o1 = o;
                if (SPLIT_OUT) {
                    if (col < 2 * D_) {   // RoPE on q and k
                        const int s = row & (S_ - 1);
                        const float2 cs = *(const float2*)&rot[s * HD_ + (col & (HD_ - 1))];
                        o0 = e * cs.x - o * cs.y;
                        o1 = e * cs.y + o * cs.x;
                    }
                    if (col < D_) {       // q: softmax scale * log2(e)
                        o0 *= QSCALE;
                        o1 *= QSCALE;
                    }
                    __half2 hv = __floats2half2_rn(o0, o1);
                    *(__half2*)&Ch[(size_t)row * N + col] = hv;
                } else {
                    float2 ov; ov.x = o0; ov.y = o1;
                    *(float2*)&C[(size_t)row * N + col] = ov;
                }
            }
        }
    }
}

// ---------------------------------------------------------------------------
// Tensor-core flash attention, fp16, exp2-domain softmax. (R9-proven)
// CTA: 128 q rows, 8 warps x 16 rows. K sub-tiles of 64 keys, 4-stage ring,
// graduated wait -> sync -> issue, one barrier per tile. 2 CTAs/SM.
// SMEM (fp16, stride 72): Q(128) | ring{K64,V64} x4
// ---------------------------------------------------------------------------
#define TSTR2   144
#define QB      (128 * TSTR2)             // 18432
#define KVST    (64 * TSTR2)              // 9216
#define STG     (2 * KVST)                // 18432 per stage
#define ATSMEM  (QB + 4 * STG)            // 92160

__global__ void __launch_bounds__(256, 2)
attn_mma(const __half* __restrict__ qkv, __half* __restrict__ oh)
{
    extern __shared__ __align__(16) char smem[];
    const uint32_t sb = smem_u32(smem);
    const int tid  = threadIdx.x;
    const int wid  = tid >> 5;
    const int lane = tid & 31;
    const int g    = lane >> 2;
    const int tg   = lane & 3;
    const int b    = blockIdx.z;
    const int h    = blockIdx.y;
    const int q0   = blockIdx.x * 128;

    // Q loader: 128 rows x 2 threads (part of commit group 0)
    {
        const int lrow = tid >> 1;
        const int lseg = (tid & 1) * 4;
        const size_t gq = ((size_t)(b * S_) + q0 + lrow) * (3 * D_) + h * HD_ + lseg * 8;
#pragma unroll
        for (int s = 0; s < 4; s++)
            CPA16(sb + (uint32_t)lrow * TSTR2 + (lseg + s) * 16, qkv + gq + s * 8);
    }

    // KV loader: 64 rows x 4 threads
    const int krow = tid >> 2;
    const int kseg = (tid & 3) * 2;
    auto issue_kv = [&](int t) {
        const size_t gk = ((size_t)(b * S_) + t * 64 + krow) * (3 * D_) + D_ + h * HD_ + kseg * 8;
        const uint32_t base = sb + QB + (t & 3) * STG + (uint32_t)krow * TSTR2 + kseg * 16;
        CPA16(base,             qkv + gk);
        CPA16(base + 16,        qkv + gk + 8);
        CPA16(base + KVST,      qkv + gk + D_);
        CPA16(base + KVST + 16, qkv + gk + D_ + 8);
        CPA_COMMIT();
    };

    issue_kv(0);   // group 0 (also contains Q)
    issue_kv(1);   // group 1
    issue_kv(2);   // group 2

    const uint32_t laneA  = (uint32_t)(lane & 15) * TSTR2 + (lane >> 4) * 16;
    const uint32_t laneB4 = (uint32_t)(lane & 7) * TSTR2 + ((lane >> 3) & 1) * 16
                          + (uint32_t)(lane >> 4) * 8 * TSTR2;
    const uint32_t laneV4 = (uint32_t)(lane & 15) * TSTR2 + (lane >> 4) * 16;

    const uint32_t aQ = sb + (uint32_t)(16 * wid) * TSTR2 + laneA;

    float o[8][4];
#pragma unroll
    for (int n = 0; n < 8; n++)
#pragma unroll
        for (int e = 0; e < 4; e++) o[n][e] = 0.0f;
    float mrow[2] = {-1e30f, -1e30f};
    float lsum[2] = {0.0f, 0.0f};

    uint32_t qf[4][4];

    const int NKT = S_ / 64;   // 32
    for (int t = 0; t < NKT; t++) {
        if (t + 2 < NKT)      CPA_WAIT(2);
        else if (t + 1 < NKT) CPA_WAIT(1);
        else                  CPA_WAIT(0);
        __syncthreads();
        if (t + 3 < NKT) issue_kv(t + 3);

        if (t == 0) {
#pragma unroll
            for (int ks = 0; ks < 4; ks++)
                LDSM_X4(qf[ks], aQ + ks * 32);
        }

        const uint32_t kb = sb + QB + (t & 3) * STG;

        // ---- scores: c[8][4] = Q(16 rows) . K^T(64 keys), log2 domain ----
        float c[8][4];
#pragma unroll
        for (int ni = 0; ni < 8; ni++)
#pragma unroll
            for (int e = 0; e < 4; e++) c[ni][e] = 0.0f;

#pragma unroll
        for (int ks = 0; ks < 4; ks++) {
#pragma unroll
            for (int nj = 0; nj < 4; nj++) {
                uint32_t bh[4];
                LDSM_X4(bh, kb + (uint32_t)(nj * 16) * TSTR2 + ks * 32 + laneB4);
                MMAH(c[2 * nj],     qf[ks], (bh + 0));
                MMAH(c[2 * nj + 1], qf[ks], (bh + 2));
            }
        }

        // ---- online softmax in exp2 domain ----
        float tmax0 = -1e30f, tmax1 = -1e30f;
#pragma unroll
        for (int ni = 0; ni < 8; ni++) {
            tmax0 = fmaxf(tmax0, fmaxf(c[ni][0], c[ni][1]));
            tmax1 = fmaxf(tmax1, fmaxf(c[ni][2], c[ni][3]));
        }
        tmax0 = fmaxf(tmax0, __shfl_xor_sync(0xffffffffu, tmax0, 1));
        tmax0 = fmaxf(tmax0, __shfl_xor_sync(0xffffffffu, tmax0, 2));
        tmax1 = fmaxf(tmax1, __shfl_xor_sync(0xffffffffu, tmax1, 1));
        tmax1 = fmaxf(tmax1, __shfl_xor_sync(0xffffffffu, tmax1, 2));

        const float mn0 = fmaxf(mrow[0], tmax0);
        const float mn1 = fmaxf(mrow[1], tmax1);
        const float al0 = exp2f(mrow[0] - mn0);
        const float al1 = exp2f(mrow[1] - mn1);
        mrow[0] = mn0;
        mrow[1] = mn1;

        float s0 = 0.0f, s1 = 0.0f;
#pragma unroll
        for (int ni = 0; ni < 8; ni++) {
            c[ni][0] = exp2f(c[ni][0] - mn0);
            c[ni][1] = exp2f(c[ni][1] - mn0);
            c[ni][2] = exp2f(c[ni][2] - mn1);
            c[ni][3] = exp2f(c[ni][3] - mn1);
            s0 += c[ni][0] + c[ni][1];
            s1 += c[ni][2] + c[ni][3];
        }
        s0 += __shfl_xor_sync(0xffffffffu, s0, 1);
        s0 += __shfl_xor_sync(0xffffffffu, s0, 2);
        s1 += __shfl_xor_sync(0xffffffffu, s1, 1);
        s1 += __shfl_xor_sync(0xffffffffu, s1, 2);
        lsum[0] = lsum[0] * al0 + s0;
        lsum[1] = lsum[1] * al1 + s1;

#pragma unroll
        for (int n = 0; n < 8; n++) {
            o[n][0] *= al0; o[n][1] *= al0;
            o[n][2] *= al1; o[n][3] *= al1;
        }

        // ---- PV: o += P(16x64) . V(64x64), P rounded to fp16 ----
        const uint32_t vbb = kb + KVST;
#pragma unroll
        for (int kj = 0; kj < 4; kj++) {
            uint32_t ap[4];
            {
                __half2 p0 = __floats2half2_rn(c[2 * kj][0],     c[2 * kj][1]);
                __half2 p1 = __floats2half2_rn(c[2 * kj][2],     c[2 * kj][3]);
                __half2 p2 = __floats2half2_rn(c[2 * kj + 1][0], c[2 * kj + 1][1]);
                __half2 p3 = __floats2half2_rn(c[2 * kj + 1][2], c[2 * kj + 1][3]);
                ap[0] = *(uint32_t*)&p0;
                ap[1] = *(uint32_t*)&p1;
                ap[2] = *(uint32_t*)&p2;
                ap[3] = *(uint32_t*)&p3;
            }
#pragma unroll
            for (int np = 0; np < 4; np++) {
                uint32_t vh[4];
                LDSM_X4T(vh, vbb + (uint32_t)(16 * kj) * TSTR2 + np * 32 + laneV4);
                MMAH(o[2 * np],     ap, (vh + 0));
                MMAH(o[2 * np + 1], ap, (vh + 2));
            }
        }
    }

    // ---- epilogue: normalize, round to fp16 ----
    const float inv0 = 1.0f / lsum[0];
    const float inv1 = 1.0f / lsum[1];
    const int r0 = b * S_ + q0 + 16 * wid + g;
    const int cb = h * HD_ + 2 * tg;
#pragma unroll
    for (int n = 0; n < 8; n++) {
        const int col = cb + 8 * n;
        __half2 hv = __floats2half2_rn(o[n][0] * inv0, o[n][1] * inv0);
        *(__half2*)&oh[(size_t)r0 * D_ + col] = hv;
        hv = __floats2half2_rn(o[n][2] * inv1, o[n][3] * inv1);
        *(__half2*)&oh[(size_t)(r0 + 8) * D_ + col] = hv;
    }
}

// ---------------------------------------------------------------------------
extern "C" void kernel_launch(void* const* d_in, const int* in_sizes, int n_in,
                              void* d_out, int out_size)
{
    const float* x     = (const float*)d_in[0];
    const float* rot   = (const float*)d_in[1];
    const float* w_qkv = (const float*)d_in[2];
    const float* b_qkv = (const float*)d_in[3];
    const float* w_o   = (const float*)d_in[4];
    const float* b_o   = (const float*)d_in[5];
    float* out = (float*)d_out;

    __half *xh, *wh, *woh, *qkv, *ah;
    cudaGetSymbolAddress((void**)&xh,  g_xh);
    cudaGetSymbolAddress((void**)&wh,  g_wh);
    cudaGetSymbolAddress((void**)&woh, g_woh);
    cudaGetSymbolAddress((void**)&qkv, g_qkv);
    cudaGetSymbolAddress((void**)&ah,  g_ah);

    static bool attr_set = false;
    if (!attr_set) {
        cudaFuncSetAttribute(gemm_mma<true>,
                             cudaFuncAttributeMaxDynamicSharedMemorySize, GSMEM);
        cudaFuncSetAttribute(gemm_mma<false>,
                             cudaFuncAttributeMaxDynamicSharedMemorySize, GSMEM);
        cudaFuncSetAttribute(attn_mma,
                             cudaFuncAttributeMaxDynamicSharedMemorySize, ATSMEM);
        attr_set = true;
    }

    // ---- prep: round x and weights to fp16 (single fused launch) ----
    prep_kernel<<<(N4_ALL + 255) / 256, 256>>>(
        (const float4*)x, (const float4*)w_qkv, (const float4*)w_o,
        (__half2*)xh, (__half2*)wh, (__half2*)woh);

    // ---- 1) QKV projection + bias + RoPE + q-scale(log2e) -> fp16 ----
    {
        dim3 grid((3 * D_) / 128, M_ / 128);
        gemm_mma<true><<<grid, 256, GSMEM>>>(xh, wh, b_qkv, rot,
                                             nullptr, qkv, M_, 3 * D_, D_);
    }

    // ---- 2) Tensor-core flash attention -> fp16 ----
    {
        dim3 grid(S_ / 128, H_, B_);
        attn_mma<<<grid, 256, ATSMEM>>>(qkv, ah);
    }

    // ---- 3) Output projection + bias -> fp32 out ----
    {
        dim3 grid(D_ / 128, M_ / 128);
        gemm_mma<false><<<grid, 256, GSMEM>>>(ah, woh, b_o, nullptr,
                                              out, nullptr, M_, D_, D_);
    }
    (void)in_sizes; (void)n_in; (void)out_size;
}